// round 2
// baseline (speedup 1.0000x reference)
#include <cuda_runtime.h>
#include <math.h>

// ---------------- problem constants ----------------
#define DIN     32
#define KLEN    512
#define PDIM    64
#define DMODEL  128
#define NLAYERS 4
#define PLEN    8
#define STRIDE  4
#define DI2     256   // DI
#define DSTATE  16
#define DCONV   4
#define DTRANK  8
#define NSEQ    127   // (512-8)/4+1
#define BATCH   32
#define MROWS   (BATCH*PDIM)     // 2048
#define RTOT    (MROWS*NSEQ)     // 260096

// ---------------- scratch (device globals; no allocation) ----------------
__device__ float g_h[BATCH*KLEN*PDIM];     // (32,512,64)
__device__ float g_e[RTOT*DMODEL];         // residual stream (2048,127,128)
__device__ float g_rstd[RTOT];             // per-row rms factor
__device__ float g_uz[RTOT*2*DI2];         // in-proj out: u|z  (2048,127,512)
__device__ float g_uact[RTOT*DI2];         // conv+silu(u)
__device__ float g_delta[RTOT*DI2];        // softplus(dt@dt_w+b)
__device__ float g_bc[RTOT*2*DSTATE];      // B(16)|C(16) per row
__device__ float g_y[RTOT*DI2];            // scan out * silu(z)
__device__ float g_val[MROWS];             // bb dot per sequence

// ---------------- 1. x@proj_w + b, LayerNorm over PD=64 ----------------
__global__ void k_proj_ln(const float* __restrict__ x, const float* __restrict__ pw,
                          const float* __restrict__ pb, const float* __restrict__ lw,
                          const float* __restrict__ lb) {
    int row = blockIdx.x;            // b*KLEN + k  (16384 rows)
    int t = threadIdx.x;             // 0..63
    __shared__ float xs[DIN];
    __shared__ float r1[64], r2[64];
    if (t < DIN) xs[t] = x[row*DIN + t];
    __syncthreads();
    float acc = pb[t];
#pragma unroll
    for (int i = 0; i < DIN; i++) acc = fmaf(xs[i], pw[i*PDIM + t], acc);
    r1[t] = acc; r2[t] = acc*acc;
    __syncthreads();
    for (int o = 32; o; o >>= 1) {
        if (t < o) { r1[t] += r1[t+o]; r2[t] += r2[t+o]; }
        __syncthreads();
    }
    float mu  = r1[0] * (1.f/64.f);
    float var = r2[0] * (1.f/64.f) - mu*mu;
    g_h[row*PDIM + t] = (acc - mu) * rsqrtf(var + 1e-5f) * lw[t] + lb[t];
}

// ---------------- 2. patch embed: e[m,n,:] = sum_p h[b, n*4+p, pd] * patch_w[p,:] + b ----------------
__global__ void k_patch(const float* __restrict__ pw, const float* __restrict__ pb) {
    int n = blockIdx.x, m = blockIdx.y;
    int t = threadIdx.x;             // dm 0..127
    __shared__ float hv[PLEN];
    int b = m >> 6, pd = m & 63;
    if (t < PLEN) hv[t] = g_h[(b*KLEN + n*STRIDE + t)*PDIM + pd];
    __syncthreads();
    float acc = pb[t];
#pragma unroll
    for (int p = 0; p < PLEN; p++) acc = fmaf(hv[p], pw[p*DMODEL + t], acc);
    g_e[(m*NSEQ + n)*DMODEL + t] = acc;
}

// ---------------- 3. per-row rms factor (norm weight folded into GEMM A-load) ----------------
__global__ void k_rms() {
    int warp = threadIdx.x >> 5, lane = threadIdx.x & 31;
    int r = blockIdx.x*8 + warp;
    const float* p = g_e + r*DMODEL;
    float s = 0.f;
#pragma unroll
    for (int i = 0; i < 4; i++) { float v = p[lane + i*32]; s = fmaf(v, v, s); }
#pragma unroll
    for (int o = 16; o; o >>= 1) s += __shfl_xor_sync(0xffffffff, s, o);
    if (lane == 0) g_rstd[r] = rsqrtf(s*(1.f/DMODEL) + 1e-5f);
}

// ---------------- 4. tiled SGEMM: MODE 0 = rms(e)@in_w -> uz ; MODE 1 = y@out_w += e ----------------
template<int MODE>
__launch_bounds__(256, 2)
__global__ void k_gemm(const float* __restrict__ W, const float* __restrict__ colScale) {
    constexpr int N = (MODE == 0) ? 2*DI2 : DMODEL;
    constexpr int K = (MODE == 0) ? DMODEL : DI2;
    const float* __restrict__ A = (MODE == 0) ? g_e : g_y;
    float* __restrict__ C       = (MODE == 0) ? g_uz : g_e;

    __shared__ float As[16][132];   // [kk][r], padded
    __shared__ float Bs[16][64];

    int tid = threadIdx.x;
    int row0 = blockIdx.y * 128;
    int col0 = blockIdx.x * 64;
    int ty = tid >> 4, tx = tid & 15;

    float acc[8][4];
#pragma unroll
    for (int i = 0; i < 8; i++)
#pragma unroll
        for (int j = 0; j < 4; j++) acc[i][j] = 0.f;

    for (int k0 = 0; k0 < K; k0 += 16) {
#pragma unroll
        for (int s = 0; s < 8; s++) {
            int i = tid + s*256;
            int r = i >> 4, kk = i & 15;
            float v = A[(row0 + r)*K + k0 + kk];
            if (MODE == 0) v *= g_rstd[row0 + r] * colScale[k0 + kk];
            As[kk][r] = v;
        }
#pragma unroll
        for (int s = 0; s < 4; s++) {
            int i = tid + s*256;
            int kk = i >> 6, nn = i & 63;
            Bs[kk][nn] = W[(k0 + kk)*N + col0 + nn];
        }
        __syncthreads();
#pragma unroll
        for (int kk = 0; kk < 16; kk++) {
            float a[8], bb[4];
#pragma unroll
            for (int i = 0; i < 8; i++) a[i] = As[kk][ty*8 + i];
#pragma unroll
            for (int j = 0; j < 4; j++) bb[j] = Bs[kk][tx*4 + j];
#pragma unroll
            for (int i = 0; i < 8; i++)
#pragma unroll
                for (int j = 0; j < 4; j++) acc[i][j] = fmaf(a[i], bb[j], acc[i][j]);
        }
        __syncthreads();
    }
#pragma unroll
    for (int i = 0; i < 8; i++) {
        int r = row0 + ty*8 + i;
#pragma unroll
        for (int j = 0; j < 4; j++) {
            int c = col0 + tx*4 + j;
            if (MODE == 1) C[r*N + c] += acc[i][j];
            else           C[r*N + c]  = acc[i][j];
        }
    }
}

// ---------------- 5. causal depthwise conv (DC=4) + silu ----------------
__global__ void k_conv_silu(const float* __restrict__ cw, const float* __restrict__ cb) {
    int m = blockIdx.x, di = threadIdx.x;
    float w0 = cw[di*DCONV+0], w1 = cw[di*DCONV+1], w2 = cw[di*DCONV+2], w3 = cw[di*DCONV+3];
    float b = cb[di];
    const float* up = g_uz + m*NSEQ*(2*DI2) + di;     // u part (cols 0..255)
    float* op = g_uact + m*NSEQ*DI2 + di;
    float x0 = 0.f, x1 = 0.f, x2 = 0.f;
    for (int n = 0; n < NSEQ; n++) {
        float x3 = up[n*(2*DI2)];
        float v = fmaf(x0, w0, fmaf(x1, w1, fmaf(x2, w2, fmaf(x3, w3, b))));
        float s = 1.f / (1.f + __expf(-v));
        op[n*DI2] = v * s;
        x0 = x1; x1 = x2; x2 = x3;
    }
}

// ---------------- 6. xproj (256->40) + dt (8->256) + softplus, writes B,C + delta ----------------
__global__ void k_xproj(const float* __restrict__ xw, const float* __restrict__ dtw,
                        const float* __restrict__ dtb) {
    __shared__ float Ash[32][65];
    __shared__ float Wsh[64][41];
    __shared__ float Dsh[32][40];
    int tid = threadIdx.x;
    int r0 = blockIdx.x * 32;
    int rloc = tid >> 3, cg = tid & 7;
    float acc[5] = {0.f, 0.f, 0.f, 0.f, 0.f};
    for (int kb = 0; kb < DI2; kb += 64) {
        __syncthreads();
#pragma unroll
        for (int s = 0; s < 8; s++) {
            int i = tid + s*256; int r = i >> 6, k = i & 63;
            Ash[r][k] = g_uact[(r0 + r)*DI2 + kb + k];
        }
#pragma unroll
        for (int s = 0; s < 10; s++) {
            int i = tid + s*256; int k = i / 40, c = i - k*40;
            Wsh[k][c] = xw[(kb + k)*40 + c];
        }
        __syncthreads();
#pragma unroll 8
        for (int k = 0; k < 64; k++) {
            float a = Ash[rloc][k];
#pragma unroll
            for (int u = 0; u < 5; u++) acc[u] = fmaf(a, Wsh[k][cg*5 + u], acc[u]);
        }
    }
    __syncthreads();
#pragma unroll
    for (int u = 0; u < 5; u++) Dsh[rloc][cg*5 + u] = acc[u];
    __syncthreads();
    // write B,C (cols 8..39)
#pragma unroll
    for (int s = 0; s < 4; s++) {
        int i = tid + s*256; int r = i >> 5, c = i & 31;
        g_bc[(r0 + r)*32 + c] = Dsh[r][8 + c];
    }
    // delta: dt(8) @ dt_w(8x256) + b, softplus
    int col = tid;
    float dw[8];
#pragma unroll
    for (int k = 0; k < 8; k++) dw[k] = dtw[k*DI2 + col];
    float db = dtb[col];
    for (int r = 0; r < 32; r++) {
        float s = db;
#pragma unroll
        for (int k = 0; k < 8; k++) s = fmaf(Dsh[r][k], dw[k], s);
        float d = (s > 20.f) ? s : log1pf(__expf(s));
        g_delta[(r0 + r)*DI2 + col] = d;
    }
}

// ---------------- 7. selective scan (block=sequence, thread=channel), fused silu(z) mult ----------------
__global__ void k_scan(const float* __restrict__ alog, const float* __restrict__ dp) {
    __shared__ float bcS[NSEQ*32];
    int m = blockIdx.x, di = threadIdx.x;
    for (int i = di; i < NSEQ*32; i += 256) bcS[i] = g_bc[m*NSEQ*32 + i];
    float A[16];
#pragma unroll
    for (int s = 0; s < 16; s++) A[s] = -__expf(alog[di*16 + s]);
    float A0 = A[0];
    bool fast = true;
#pragma unroll
    for (int s = 1; s < 16; s++) {
        float tgt = (float)(s + 1) * A0;
        if (fabsf(A[s] - tgt) > 1e-4f * fabsf(tgt)) fast = false;
    }
    float Dv = dp[di];
    float h[16];
#pragma unroll
    for (int s = 0; s < 16; s++) h[s] = 0.f;
    __syncthreads();
    const float* dptr = g_delta + m*NSEQ*DI2 + di;
    const float* uptr = g_uact  + m*NSEQ*DI2 + di;
    const float* zptr = g_uz    + m*NSEQ*(2*DI2) + DI2 + di;
    float* yptr       = g_y     + m*NSEQ*DI2 + di;
    if (fast) {
        for (int n = 0; n < NSEQ; n++) {
            float d = dptr[n*DI2], u = uptr[n*DI2];
            float dlu = d*u;
            float q = __expf(d*A0);
            float p = q, acc = 0.f;
            const float* bcp = bcS + n*32;
#pragma unroll
            for (int s = 0; s < 16; s++) {
                h[s] = fmaf(p, h[s], dlu*bcp[s]);
                acc  = fmaf(h[s], bcp[16 + s], acc);
                p *= q;
            }
            float z = zptr[n*(2*DI2)];
            float sz = z / (1.f + __expf(-z));
            yptr[n*DI2] = (acc + u*Dv) * sz;
        }
    } else {
        for (int n = 0; n < NSEQ; n++) {
            float d = dptr[n*DI2], u = uptr[n*DI2];
            float dlu = d*u;
            float acc = 0.f;
            const float* bcp = bcS + n*32;
#pragma unroll
            for (int s = 0; s < 16; s++) {
                float dA = __expf(d*A[s]);
                h[s] = fmaf(dA, h[s], dlu*bcp[s]);
                acc  = fmaf(h[s], bcp[16 + s], acc);
            }
            float z = zptr[n*(2*DI2)];
            float sz = z / (1.f + __expf(-z));
            yptr[n*DI2] = (acc + u*Dv) * sz;
        }
    }
}

// ---------------- 8. final rms + bb dot per sequence ----------------
__global__ void k_final(const float* __restrict__ fnw, const float* __restrict__ bbw,
                        const float* __restrict__ bbb) {
    int m = blockIdx.x, t = threadIdx.x;   // 128 threads
    int w = t >> 5, lane = t & 31;
    __shared__ float red[2][4];
    float fn = fnw[t];
    float acc = 0.f;
    for (int n = 0; n < NSEQ; n++) {
        float v = g_e[(m*NSEQ + n)*DMODEL + t];
        float s = v*v;
#pragma unroll
        for (int o = 16; o; o >>= 1) s += __shfl_xor_sync(0xffffffff, s, o);
        if (lane == 0) red[n & 1][w] = s;
        __syncthreads();
        float ss = red[n & 1][0] + red[n & 1][1] + red[n & 1][2] + red[n & 1][3];
        float rs = rsqrtf(ss*(1.f/DMODEL) + 1e-5f);
        acc = fmaf(v*rs*fn, bbw[n*DMODEL + t], acc);
    }
#pragma unroll
    for (int o = 16; o; o >>= 1) acc += __shfl_xor_sync(0xffffffff, acc, o);
    __shared__ float fr[4];
    if (lane == 0) fr[w] = acc;
    __syncthreads();
    if (t == 0) g_val[m] = fr[0] + fr[1] + fr[2] + fr[3] + bbb[0];
}

// ---------------- 9. head: (32,64) @ (64,2) + b ----------------
__global__ void k_head(const float* __restrict__ hw, const float* __restrict__ hb,
                       float* __restrict__ out) {
    int t = threadIdx.x;  // 64
    int b = t >> 1, o = t & 1;
    float s = hb[o];
    for (int pd = 0; pd < 64; pd++) s = fmaf(g_val[b*64 + pd], hw[pd*2 + o], s);
    out[t] = s;
}

// ---------------- launch ----------------
extern "C" void kernel_launch(void* const* d_in, const int* in_sizes, int n_in,
                              void* d_out, int out_size) {
    const float* x       = (const float*)d_in[0];
    const float* proj_w  = (const float*)d_in[1];
    const float* proj_b  = (const float*)d_in[2];
    const float* ln_w    = (const float*)d_in[3];
    const float* ln_b    = (const float*)d_in[4];
    const float* patch_w = (const float*)d_in[5];
    const float* patch_b = (const float*)d_in[6];
    const float* in_w    = (const float*)d_in[7];
    const float* conv_w  = (const float*)d_in[8];
    const float* conv_b  = (const float*)d_in[9];
    const float* xproj_w = (const float*)d_in[10];
    const float* dt_w    = (const float*)d_in[11];
    const float* dt_b    = (const float*)d_in[12];
    const float* A_log   = (const float*)d_in[13];
    const float* Dp      = (const float*)d_in[14];
    const float* out_w   = (const float*)d_in[15];
    const float* norm_w  = (const float*)d_in[16];
    const float* fnorm_w = (const float*)d_in[17];
    const float* bb_w    = (const float*)d_in[18];
    const float* bb_b    = (const float*)d_in[19];
    const float* head_w  = (const float*)d_in[20];
    const float* head_b  = (const float*)d_in[21];

    k_proj_ln<<<BATCH*KLEN, 64>>>(x, proj_w, proj_b, ln_w, ln_b);
    k_patch<<<dim3(NSEQ, MROWS), DMODEL>>>(patch_w, patch_b);

    for (int l = 0; l < NLAYERS; l++) {
        k_rms<<<RTOT/8, 256>>>();
        k_gemm<0><<<dim3((2*DI2)/64, RTOT/128), 256>>>(in_w + l*DMODEL*2*DI2,
                                                       norm_w + l*DMODEL);
        k_conv_silu<<<MROWS, DI2>>>(conv_w + l*DI2*DCONV, conv_b + l*DI2);
        k_xproj<<<RTOT/32, 256>>>(xproj_w + l*DI2*40, dt_w + l*DTRANK*DI2, dt_b + l*DI2);
        k_scan<<<MROWS, DI2>>>(A_log + l*DI2*DSTATE, Dp + l*DI2);
        k_gemm<1><<<dim3(DMODEL/64, RTOT/128), 256>>>(out_w + l*DI2*DMODEL, nullptr);
    }

    k_final<<<MROWS, DMODEL>>>(fnorm_w, bb_w, bb_b);
    k_head<<<1, 64>>>(head_w, head_b, (float*)d_out);
}